// round 8
// baseline (speedup 1.0000x reference)
#include <cuda_runtime.h>
#include <cuda_bf16.h>
#include <math.h>

#define N_BINS 15
#define NBLK   (148 * 4)      // main-kernel grid (c100 path)
#define PCOLS  48             // padded partial row: 15 cnt, 15 conf, 15 acc, 1 bri

// Per-block partials: overwritten fully every launch -> no init kernel needed.
__device__ float g_part[NBLK][PCOLS];
__device__ unsigned int g_ticket;   // zero-init; last block resets to 0 each launch

// C==100 specialized: 8 lanes per row, 4 rows per warp, double-buffered,
// fused finalize in the last block (threadfence-reduction pattern).
__global__ void __launch_bounds__(256, 4) ece_main_c100(
    const float4* __restrict__ probs4,
    const int* __restrict__ labels,
    float* __restrict__ out,
    int N)
{
    __shared__ float s_cnt[N_BINS], s_cf[N_BINS], s_ac[N_BINS], s_bri;

    if (threadIdx.x < N_BINS) {
        s_cnt[threadIdx.x] = 0.f; s_cf[threadIdx.x] = 0.f; s_ac[threadIdx.x] = 0.f;
    }
    if (threadIdx.x == 0) s_bri = 0.f;
    __syncthreads();

    const int lane  = threadIdx.x & 31;
    const int k     = lane & 7;          // lane within 8-lane row-group
    const int g     = lane >> 3;         // row-group (0..3)
    const int gbase = lane & 24;
    const int warp  = (blockIdx.x * blockDim.x + threadIdx.x) >> 5;
    const int nwarp = (gridDim.x * blockDim.x) >> 5;
    const int step  = nwarp * 4;

    float a_cnt = 0.f, a_cf = 0.f, a_ac = 0.f;   // lane k owns bin k
    float b_cnt = 0.f, b_cf = 0.f, b_ac = 0.f;   // lane k owns bin k+8 (k<7)
    float abri  = 0.f;

    float4 c0, c1, c2, c3, n0, n1, n2, n3;
    int clab = 0, nlab = 0;
    bool cval = false, nval = false;

    int q0 = warp * 4;
    {
        int row = q0 + g;
        cval = (q0 < N) && (row < N);
        if (cval) {
            const float4* rp = probs4 + (size_t)row * 25;
            c0 = rp[k]; c1 = rp[k + 8]; c2 = rp[k + 16];
            c3 = (k == 0) ? rp[24] : make_float4(0.f, 0.f, 0.f, 0.f);
            clab = labels[row];
        } else {
            c0 = c1 = c2 = c3 = make_float4(0.f, 0.f, 0.f, 0.f);
        }
    }

    for (int q = q0; q < N; q += step) {
        int nq = q + step;
        int nrow = nq + g;
        nval = (nq < N) && (nrow < N);
        if (nval) {
            const float4* rp = probs4 + (size_t)nrow * 25;
            n0 = rp[k]; n1 = rp[k + 8]; n2 = rp[k + 16];
            n3 = (k == 0) ? rp[24] : make_float4(0.f, 0.f, 0.f, 0.f);
            nlab = labels[nrow];
        }

        float s, sq, m; int mi;
        {
            int base = k * 4;
            s  = (c0.x + c0.y) + (c0.z + c0.w);
            sq = (c0.x * c0.x + c0.y * c0.y) + (c0.z * c0.z + c0.w * c0.w);
            m = c0.x; mi = base;
            if (c0.y > m) { m = c0.y; mi = base + 1; }
            if (c0.z > m) { m = c0.z; mi = base + 2; }
            if (c0.w > m) { m = c0.w; mi = base + 3; }
        }
        {
            int base = (k + 8) * 4;
            s  += (c1.x + c1.y) + (c1.z + c1.w);
            sq += (c1.x * c1.x + c1.y * c1.y) + (c1.z * c1.z + c1.w * c1.w);
            if (c1.x > m) { m = c1.x; mi = base; }
            if (c1.y > m) { m = c1.y; mi = base + 1; }
            if (c1.z > m) { m = c1.z; mi = base + 2; }
            if (c1.w > m) { m = c1.w; mi = base + 3; }
        }
        {
            int base = (k + 16) * 4;
            s  += (c2.x + c2.y) + (c2.z + c2.w);
            sq += (c2.x * c2.x + c2.y * c2.y) + (c2.z * c2.z + c2.w * c2.w);
            if (c2.x > m) { m = c2.x; mi = base; }
            if (c2.y > m) { m = c2.y; mi = base + 1; }
            if (c2.z > m) { m = c2.z; mi = base + 2; }
            if (c2.w > m) { m = c2.w; mi = base + 3; }
        }
        if (k == 0) {
            s  += (c3.x + c3.y) + (c3.z + c3.w);
            sq += (c3.x * c3.x + c3.y * c3.y) + (c3.z * c3.z + c3.w * c3.w);
            if (c3.x > m) { m = c3.x; mi = 96; }
            if (c3.y > m) { m = c3.y; mi = 97; }
            if (c3.z > m) { m = c3.z; mi = 98; }
            if (c3.w > m) { m = c3.w; mi = 99; }
        }

        #pragma unroll
        for (int off = 4; off >= 1; off >>= 1) {
            s  += __shfl_xor_sync(0xffffffffu, s,  off);
            sq += __shfl_xor_sync(0xffffffffu, sq, off);
            float om = __shfl_xor_sync(0xffffffffu, m,  off);
            int   oi = __shfl_xor_sync(0xffffffffu, mi, off);
            if (om > m || (om == m && oi < mi)) { m = om; mi = oi; }
        }

        // p[label] from registers via shuffle
        int lab  = clab;
        int labc = lab < 0 ? 0 : (lab > 99 ? 99 : lab);
        int idx4 = labc >> 2, comp = labc & 3;
        int slot = idx4 >> 3;
        int owner = (slot == 3) ? 0 : (idx4 & 7);
        float4 vs = (slot == 0) ? c0 : (slot == 1) ? c1 : (slot == 2) ? c2 : c3;
        float cand = (comp == 0) ? vs.x : (comp == 1) ? vs.y : (comp == 2) ? vs.z : vs.w;
        float pl = __shfl_sync(0xffffffffu, cand, gbase | owner);

        float inv  = 1.f / s;
        float conf = m * inv;
        float bri  = sq * inv * inv - 2.f * pl * inv + 1.f;
        float hit  = (mi == lab) ? 1.f : 0.f;
        int bin = (int)ceilf(conf * (float)N_BINS) - 1;
        bin = bin < 0 ? 0 : (bin > N_BINS - 1 ? N_BINS - 1 : bin);

        if (cval) {
            if (bin == k)     { a_cnt += 1.f; a_cf += conf; a_ac += hit; }
            if (bin == k + 8) { b_cnt += 1.f; b_cf += conf; b_ac += hit; }
            if (k == 0) abri += bri;
        }

        c0 = n0; c1 = n1; c2 = n2; c3 = n3; clab = nlab; cval = nval;
    }

    // cross-group reduction (lane bits 3,4)
    #pragma unroll
    for (int off = 8; off <= 16; off <<= 1) {
        a_cnt += __shfl_xor_sync(0xffffffffu, a_cnt, off);
        a_cf  += __shfl_xor_sync(0xffffffffu, a_cf,  off);
        a_ac  += __shfl_xor_sync(0xffffffffu, a_ac,  off);
        b_cnt += __shfl_xor_sync(0xffffffffu, b_cnt, off);
        b_cf  += __shfl_xor_sync(0xffffffffu, b_cf,  off);
        b_ac  += __shfl_xor_sync(0xffffffffu, b_ac,  off);
        abri  += __shfl_xor_sync(0xffffffffu, abri,  off);
    }

    if (lane < 8 && a_cnt > 0.f) {
        atomicAdd(&s_cnt[lane], a_cnt);
        atomicAdd(&s_cf[lane],  a_cf);
        atomicAdd(&s_ac[lane],  a_ac);
    }
    if (lane < 7 && b_cnt > 0.f) {
        atomicAdd(&s_cnt[lane + 8], b_cnt);
        atomicAdd(&s_cf[lane + 8],  b_cf);
        atomicAdd(&s_ac[lane + 8],  b_ac);
    }
    if (lane == 0 && abri != 0.f) atomicAdd(&s_bri, abri);
    __syncthreads();

    // write this block's partial slot (full overwrite -> deterministic)
    {
        int t = threadIdx.x;
        if (t < N_BINS) {
            g_part[blockIdx.x][t]              = s_cnt[t];
            g_part[blockIdx.x][t + N_BINS]     = s_cf[t];
            g_part[blockIdx.x][t + 2 * N_BINS] = s_ac[t];
        }
        if (t == 0) g_part[blockIdx.x][45] = s_bri;
    }

    // ---- fused finalize: last block reduces all partials (L2-hot) ----
    __shared__ bool is_last;
    __threadfence();
    if (threadIdx.x == 0) {
        unsigned int tk = atomicAdd(&g_ticket, 1u);
        is_last = (tk == gridDim.x - 1);
    }
    __syncthreads();

    if (is_last) {
        if (threadIdx.x == 0) g_ticket = 0;   // reset for next graph replay
        __shared__ double col[46];
        const int c     = threadIdx.x & 63;   // column (46 used)
        const int chunk = threadIdx.x >> 6;   // 0..3

        if (threadIdx.x < 46) col[threadIdx.x] = 0.0;
        __syncthreads();

        double acc = 0.0;
        if (c < 46) {
            #pragma unroll 8
            for (int b = chunk; b < NBLK; b += 4)
                acc += (double)g_part[b][c];
            atomicAdd(&col[c], acc);
        }
        __syncthreads();

        if (threadIdx.x == 0) {
            double ece = 0.0, mx = 0.0;
            double invN = 1.0 / (double)N;
            #pragma unroll
            for (int b = 0; b < N_BINS; b++) {
                double cc = col[b];
                if (cc > 0.0) {
                    double gap = fabs(col[b + N_BINS] / cc - col[b + 2 * N_BINS] / cc);
                    ece += gap * cc * invN;
                    if (gap > mx) mx = gap;
                }
            }
            out[0] = (float)ece;
            out[1] = (float)mx;
            out[2] = (float)(col[45] * invN);
        }
    }
}

// Generic fallback: warp-per-row, same fused-finalize scheme.
__global__ void ece_main_generic(const float* __restrict__ probs,
                                 const int* __restrict__ labels,
                                 float* __restrict__ out,
                                 int N, int C) {
    __shared__ float s_cnt[N_BINS], s_cf[N_BINS], s_ac[N_BINS], s_bri;
    if (threadIdx.x < N_BINS) {
        s_cnt[threadIdx.x] = 0.f; s_cf[threadIdx.x] = 0.f; s_ac[threadIdx.x] = 0.f;
    }
    if (threadIdx.x == 0) s_bri = 0.f;
    __syncthreads();

    const int lane  = threadIdx.x & 31;
    const int warp  = (blockIdx.x * blockDim.x + threadIdx.x) >> 5;
    const int nwarp = (gridDim.x * blockDim.x) >> 5;

    float acc_count = 0.f, acc_conf = 0.f, acc_acc = 0.f, acc_bri = 0.f;

    for (int row = warp; row < N; row += nwarp) {
        const float* rp = probs + (size_t)row * C;
        float s = 0.f, sq = 0.f, m = -1.f;
        int mi = 0x7fffffff;
        for (int c = lane; c < C; c += 32) {
            float x = rp[c];
            s += x; sq += x * x;
            if (x > m) { m = x; mi = c; }
        }
        #pragma unroll
        for (int off = 16; off >= 1; off >>= 1) {
            s  += __shfl_xor_sync(0xffffffffu, s,  off);
            sq += __shfl_xor_sync(0xffffffffu, sq, off);
            float om = __shfl_xor_sync(0xffffffffu, m,  off);
            int   oi = __shfl_xor_sync(0xffffffffu, mi, off);
            if (om > m || (om == m && oi < mi)) { m = om; mi = oi; }
        }
        int lab = labels[row];
        int labc = lab < 0 ? 0 : (lab >= C ? C - 1 : lab);
        float pl = rp[labc];
        float inv  = 1.f / s;
        float conf = m * inv;
        float bri  = sq * inv * inv - 2.f * pl * inv + 1.f;
        int   hit  = (mi == lab) ? 1 : 0;
        int bin = (int)ceilf(conf * (float)N_BINS) - 1;
        bin = bin < 0 ? 0 : (bin > N_BINS - 1 ? N_BINS - 1 : bin);
        if (lane == bin) { acc_count += 1.f; acc_conf += conf; acc_acc += (float)hit; }
        if (lane == 0) acc_bri += bri;
    }

    if (lane < N_BINS && acc_count > 0.f) {
        atomicAdd(&s_cnt[lane], acc_count);
        atomicAdd(&s_cf[lane],  acc_conf);
        atomicAdd(&s_ac[lane],  acc_acc);
    }
    if (lane == 0 && acc_bri != 0.f) atomicAdd(&s_bri, acc_bri);
    __syncthreads();

    {
        int t = threadIdx.x;
        if (t < N_BINS) {
            g_part[blockIdx.x][t]              = s_cnt[t];
            g_part[blockIdx.x][t + N_BINS]     = s_cf[t];
            g_part[blockIdx.x][t + 2 * N_BINS] = s_ac[t];
        }
        if (t == 0) g_part[blockIdx.x][45] = s_bri;
    }

    __shared__ bool is_last;
    __threadfence();
    if (threadIdx.x == 0) {
        unsigned int tk = atomicAdd(&g_ticket, 1u);
        is_last = (tk == gridDim.x - 1);
    }
    __syncthreads();

    if (is_last) {
        if (threadIdx.x == 0) g_ticket = 0;
        __shared__ double col[46];
        const int c     = threadIdx.x & 63;
        const int chunk = threadIdx.x >> 6;

        if (threadIdx.x < 46) col[threadIdx.x] = 0.0;
        __syncthreads();

        double acc = 0.0;
        if (c < 46) {
            for (int b = chunk; b < (int)gridDim.x; b += 4)
                acc += (double)g_part[b][c];
            atomicAdd(&col[c], acc);
        }
        __syncthreads();

        if (threadIdx.x == 0) {
            double ece = 0.0, mx = 0.0;
            double invN = 1.0 / (double)N;
            #pragma unroll
            for (int b = 0; b < N_BINS; b++) {
                double cc = col[b];
                if (cc > 0.0) {
                    double gap = fabs(col[b + N_BINS] / cc - col[b + 2 * N_BINS] / cc);
                    ece += gap * cc * invN;
                    if (gap > mx) mx = gap;
                }
            }
            out[0] = (float)ece;
            out[1] = (float)mx;
            out[2] = (float)(col[45] * invN);
        }
    }
}

extern "C" void kernel_launch(void* const* d_in, const int* in_sizes, int n_in,
                              void* d_out, int out_size) {
    int i_probs = 0, i_labels = 1;
    if (n_in >= 2 && in_sizes[1] > in_sizes[0]) { i_probs = 1; i_labels = 0; }
    const float* probs  = (const float*)d_in[i_probs];
    const int*   labels = (const int*)d_in[i_labels];
    int N = in_sizes[i_labels];
    int C = in_sizes[i_probs] / N;
    float* out = (float*)d_out;

    if (C == 100) {
        ece_main_c100<<<NBLK, 256>>>((const float4*)probs, labels, out, N);
    } else {
        ece_main_generic<<<NBLK, 256>>>(probs, labels, out, N, C);
    }
}

// round 12
// speedup vs baseline: 1.0050x; 1.0050x over previous
#include <cuda_runtime.h>
#include <cuda_bf16.h>
#include <math.h>

#define N_BINS 15
#define NBLK   (148 * 4)
#define PCOLS  48

__device__ float g_part[NBLK][PCOLS];
__device__ unsigned int g_ticket;   // zero-init; last block resets each launch

typedef unsigned long long ull;

__device__ __forceinline__ ull pk2(float lo, float hi) {
    ull r; asm("mov.b64 %0, {%1, %2};" : "=l"(r) : "f"(lo), "f"(hi)); return r;
}
__device__ __forceinline__ void upk2(ull v, float& lo, float& hi) {
    asm("mov.b64 {%0, %1}, %2;" : "=f"(lo), "=f"(hi) : "l"(v));
}
__device__ __forceinline__ ull addx2(ull a, ull b) {
    ull r; asm("add.rn.f32x2 %0, %1, %2;" : "=l"(r) : "l"(a), "l"(b)); return r;
}
__device__ __forceinline__ ull fmaxx2(ull a, ull c) {  // a*a + c
    ull r; asm("fma.rn.f32x2 %0, %1, %2, %3;" : "=l"(r) : "l"(a), "l"(a), "l"(c)); return r;
}

// C==100: 8 lanes/row, 4 rows/warp, double-buffered, no-argmax trick,
// packed f32x2 sum/sumsq, fused last-block finalize.
__global__ void __launch_bounds__(256, 4) ece_main_c100(
    const float4* __restrict__ probs4,
    const int* __restrict__ labels,
    float* __restrict__ out,
    int N)
{
    __shared__ float s_cnt[N_BINS], s_cf[N_BINS], s_ac[N_BINS], s_bri;
    if (threadIdx.x < N_BINS) {
        s_cnt[threadIdx.x] = 0.f; s_cf[threadIdx.x] = 0.f; s_ac[threadIdx.x] = 0.f;
    }
    if (threadIdx.x == 0) s_bri = 0.f;
    __syncthreads();

    const int lane  = threadIdx.x & 31;
    const int k     = lane & 7;
    const int g     = lane >> 3;
    const int gbase = lane & 24;
    const int warp  = (blockIdx.x * blockDim.x + threadIdx.x) >> 5;
    const int nwarp = (gridDim.x * blockDim.x) >> 5;
    const int step  = nwarp * 4;

    float a_cnt = 0.f, a_cf = 0.f, a_ac = 0.f;   // lane k owns bin k
    float b_cnt = 0.f, b_cf = 0.f, b_ac = 0.f;   // lane k owns bin k+8 (k<7)
    float abri  = 0.f;

    float4 c0, c1, c2, c3, n0, n1, n2, n3;
    int clab = 0, nlab = 0;
    bool cval = false, nval = false;

    int q0 = warp * 4;
    {
        int row = q0 + g;
        cval = (q0 < N) && (row < N);
        if (cval) {
            const float4* rp = probs4 + (size_t)row * 25;
            c0 = rp[k]; c1 = rp[k + 8]; c2 = rp[k + 16];
            c3 = (k == 0) ? rp[24] : make_float4(0.f, 0.f, 0.f, 0.f);
            clab = labels[row];
        } else {
            c0 = c1 = c2 = c3 = make_float4(0.f, 0.f, 0.f, 0.f);
        }
    }

    for (int q = q0; q < N; q += step) {
        int nq = q + step;
        int nrow = nq + g;
        nval = (nq < N) && (nrow < N);
        if (nval) {
            const float4* rp = probs4 + (size_t)nrow * 25;
            n0 = rp[k]; n1 = rp[k + 8]; n2 = rp[k + 16];
            n3 = (k == 0) ? rp[24] : make_float4(0.f, 0.f, 0.f, 0.f);
            nlab = labels[nrow];
        }

        // packed sum / sumsq + scalar max (zeros in c3 for k!=0 are harmless)
        ull v01 = pk2(c0.x, c0.y), v23 = pk2(c0.z, c0.w);
        ull s2  = addx2(v01, v23);
        ull sq2 = fmaxx2(v01, fmaxx2(v23, 0ull));
        float m = fmaxf(fmaxf(c0.x, c0.y), fmaxf(c0.z, c0.w));

        v01 = pk2(c1.x, c1.y); v23 = pk2(c1.z, c1.w);
        s2  = addx2(s2, addx2(v01, v23));
        sq2 = fmaxx2(v01, fmaxx2(v23, sq2));
        m = fmaxf(m, fmaxf(fmaxf(c1.x, c1.y), fmaxf(c1.z, c1.w)));

        v01 = pk2(c2.x, c2.y); v23 = pk2(c2.z, c2.w);
        s2  = addx2(s2, addx2(v01, v23));
        sq2 = fmaxx2(v01, fmaxx2(v23, sq2));
        m = fmaxf(m, fmaxf(fmaxf(c2.x, c2.y), fmaxf(c2.z, c2.w)));

        v01 = pk2(c3.x, c3.y); v23 = pk2(c3.z, c3.w);
        s2  = addx2(s2, addx2(v01, v23));
        sq2 = fmaxx2(v01, fmaxx2(v23, sq2));
        m = fmaxf(m, fmaxf(fmaxf(c3.x, c3.y), fmaxf(c3.z, c3.w)));

        // butterfly within 8-lane group (packed s/sq, scalar m)
        #pragma unroll
        for (int off = 4; off >= 1; off >>= 1) {
            s2  = addx2(s2,  __shfl_xor_sync(0xffffffffu, s2,  off));
            sq2 = addx2(sq2, __shfl_xor_sync(0xffffffffu, sq2, off));
            m   = fmaxf(m, __shfl_xor_sync(0xffffffffu, m, off));
        }
        float slo, shi, qlo, qhi;
        upk2(s2, slo, shi); upk2(sq2, qlo, qhi);
        float s  = slo + shi;
        float sq = qlo + qhi;

        // p[label] from registers via shuffle
        int lab  = clab;
        int labc = lab < 0 ? 0 : (lab > 99 ? 99 : lab);
        int idx4 = labc >> 2, comp = labc & 3;
        int slot = idx4 >> 3;
        int owner = (slot == 3) ? 0 : (idx4 & 7);
        float4 vs = (slot == 0) ? c0 : (slot == 1) ? c1 : (slot == 2) ? c2 : c3;
        float cand = (comp == 0) ? vs.x : (comp == 1) ? vs.y : (comp == 2) ? vs.z : vs.w;
        float pl = __shfl_sync(0xffffffffu, cand, gbase | owner);

        float inv  = __fdividef(1.f, s);
        float conf = m * inv;
        float bri  = sq * inv * inv - 2.f * pl * inv + 1.f;
        float hit  = (pl == m) ? 1.f : 0.f;   // argmax==label  <=>  p[label]==max (ties ~0)
        int bin = __float2int_ru(conf * (float)N_BINS) - 1;
        bin = bin < 0 ? 0 : (bin > N_BINS - 1 ? N_BINS - 1 : bin);

        if (cval) {
            if (bin == k)     { a_cnt += 1.f; a_cf += conf; a_ac += hit; }
            if (bin == k + 8) { b_cnt += 1.f; b_cf += conf; b_ac += hit; }
            if (k == 0) abri += bri;
        }

        c0 = n0; c1 = n1; c2 = n2; c3 = n3; clab = nlab; cval = nval;
    }

    // cross-group reduction (lane bits 3,4)
    #pragma unroll
    for (int off = 8; off <= 16; off <<= 1) {
        a_cnt += __shfl_xor_sync(0xffffffffu, a_cnt, off);
        a_cf  += __shfl_xor_sync(0xffffffffu, a_cf,  off);
        a_ac  += __shfl_xor_sync(0xffffffffu, a_ac,  off);
        b_cnt += __shfl_xor_sync(0xffffffffu, b_cnt, off);
        b_cf  += __shfl_xor_sync(0xffffffffu, b_cf,  off);
        b_ac  += __shfl_xor_sync(0xffffffffu, b_ac,  off);
        abri  += __shfl_xor_sync(0xffffffffu, abri,  off);
    }

    if (lane < 8 && a_cnt > 0.f) {
        atomicAdd(&s_cnt[lane], a_cnt);
        atomicAdd(&s_cf[lane],  a_cf);
        atomicAdd(&s_ac[lane],  a_ac);
    }
    if (lane < 7 && b_cnt > 0.f) {
        atomicAdd(&s_cnt[lane + 8], b_cnt);
        atomicAdd(&s_cf[lane + 8],  b_cf);
        atomicAdd(&s_ac[lane + 8],  b_ac);
    }
    if (lane == 0 && abri != 0.f) atomicAdd(&s_bri, abri);
    __syncthreads();

    {
        int t = threadIdx.x;
        if (t < N_BINS) {
            g_part[blockIdx.x][t]              = s_cnt[t];
            g_part[blockIdx.x][t + N_BINS]     = s_cf[t];
            g_part[blockIdx.x][t + 2 * N_BINS] = s_ac[t];
        }
        if (t == 0) g_part[blockIdx.x][45] = s_bri;
    }

    // ---- fused finalize: last block reduces all partials (L2-hot) ----
    __shared__ bool is_last;
    __threadfence();
    if (threadIdx.x == 0) {
        unsigned int tk = atomicAdd(&g_ticket, 1u);
        is_last = (tk == gridDim.x - 1);
    }
    __syncthreads();

    if (is_last) {
        if (threadIdx.x == 0) g_ticket = 0;
        __shared__ double col[46];
        const int c     = threadIdx.x & 63;
        const int chunk = threadIdx.x >> 6;

        if (threadIdx.x < 46) col[threadIdx.x] = 0.0;
        __syncthreads();

        double acc = 0.0;
        if (c < 46) {
            #pragma unroll 8
            for (int b = chunk; b < NBLK; b += 4)
                acc += (double)g_part[b][c];
            atomicAdd(&col[c], acc);
        }
        __syncthreads();

        if (threadIdx.x == 0) {
            double ece = 0.0, mx = 0.0;
            double invN = 1.0 / (double)N;
            #pragma unroll
            for (int b = 0; b < N_BINS; b++) {
                double cc = col[b];
                if (cc > 0.0) {
                    double gap = fabs(col[b + N_BINS] / cc - col[b + 2 * N_BINS] / cc);
                    ece += gap * cc * invN;
                    if (gap > mx) mx = gap;
                }
            }
            out[0] = (float)ece;
            out[1] = (float)mx;
            out[2] = (float)(col[45] * invN);
        }
    }
}

// Generic fallback: warp-per-row, fused finalize.
__global__ void ece_main_generic(const float* __restrict__ probs,
                                 const int* __restrict__ labels,
                                 float* __restrict__ out,
                                 int N, int C) {
    __shared__ float s_cnt[N_BINS], s_cf[N_BINS], s_ac[N_BINS], s_bri;
    if (threadIdx.x < N_BINS) {
        s_cnt[threadIdx.x] = 0.f; s_cf[threadIdx.x] = 0.f; s_ac[threadIdx.x] = 0.f;
    }
    if (threadIdx.x == 0) s_bri = 0.f;
    __syncthreads();

    const int lane  = threadIdx.x & 31;
    const int warp  = (blockIdx.x * blockDim.x + threadIdx.x) >> 5;
    const int nwarp = (gridDim.x * blockDim.x) >> 5;

    float acc_count = 0.f, acc_conf = 0.f, acc_acc = 0.f, acc_bri = 0.f;

    for (int row = warp; row < N; row += nwarp) {
        const float* rp = probs + (size_t)row * C;
        float s = 0.f, sq = 0.f, m = -1.f;
        for (int c = lane; c < C; c += 32) {
            float x = rp[c];
            s += x; sq += x * x;
            m = fmaxf(m, x);
        }
        #pragma unroll
        for (int off = 16; off >= 1; off >>= 1) {
            s  += __shfl_xor_sync(0xffffffffu, s,  off);
            sq += __shfl_xor_sync(0xffffffffu, sq, off);
            m = fmaxf(m, __shfl_xor_sync(0xffffffffu, m, off));
        }
        int lab = labels[row];
        int labc = lab < 0 ? 0 : (lab >= C ? C - 1 : lab);
        float pl = rp[labc];
        float inv  = __fdividef(1.f, s);
        float conf = m * inv;
        float bri  = sq * inv * inv - 2.f * pl * inv + 1.f;
        float hit  = (pl == m) ? 1.f : 0.f;
        int bin = __float2int_ru(conf * (float)N_BINS) - 1;
        bin = bin < 0 ? 0 : (bin > N_BINS - 1 ? N_BINS - 1 : bin);
        if (lane == bin) { acc_count += 1.f; acc_conf += conf; acc_acc += hit; }
        if (lane == 0) acc_bri += bri;
    }

    if (lane < N_BINS && acc_count > 0.f) {
        atomicAdd(&s_cnt[lane], acc_count);
        atomicAdd(&s_cf[lane],  acc_conf);
        atomicAdd(&s_ac[lane],  acc_acc);
    }
    if (lane == 0 && acc_bri != 0.f) atomicAdd(&s_bri, acc_bri);
    __syncthreads();

    {
        int t = threadIdx.x;
        if (t < N_BINS) {
            g_part[blockIdx.x][t]              = s_cnt[t];
            g_part[blockIdx.x][t + N_BINS]     = s_cf[t];
            g_part[blockIdx.x][t + 2 * N_BINS] = s_ac[t];
        }
        if (t == 0) g_part[blockIdx.x][45] = s_bri;
    }

    __shared__ bool is_last;
    __threadfence();
    if (threadIdx.x == 0) {
        unsigned int tk = atomicAdd(&g_ticket, 1u);
        is_last = (tk == gridDim.x - 1);
    }
    __syncthreads();

    if (is_last) {
        if (threadIdx.x == 0) g_ticket = 0;
        __shared__ double col[46];
        const int c     = threadIdx.x & 63;
        const int chunk = threadIdx.x >> 6;

        if (threadIdx.x < 46) col[threadIdx.x] = 0.0;
        __syncthreads();

        double acc = 0.0;
        if (c < 46) {
            for (int b = chunk; b < (int)gridDim.x; b += 4)
                acc += (double)g_part[b][c];
            atomicAdd(&col[c], acc);
        }
        __syncthreads();

        if (threadIdx.x == 0) {
            double ece = 0.0, mx = 0.0;
            double invN = 1.0 / (double)N;
            #pragma unroll
            for (int b = 0; b < N_BINS; b++) {
                double cc = col[b];
                if (cc > 0.0) {
                    double gap = fabs(col[b + N_BINS] / cc - col[b + 2 * N_BINS] / cc);
                    ece += gap * cc * invN;
                    if (gap > mx) mx = gap;
                }
            }
            out[0] = (float)ece;
            out[1] = (float)mx;
            out[2] = (float)(col[45] * invN);
        }
    }
}

extern "C" void kernel_launch(void* const* d_in, const int* in_sizes, int n_in,
                              void* d_out, int out_size) {
    int i_probs = 0, i_labels = 1;
    if (n_in >= 2 && in_sizes[1] > in_sizes[0]) { i_probs = 1; i_labels = 0; }
    const float* probs  = (const float*)d_in[i_probs];
    const int*   labels = (const int*)d_in[i_labels];
    int N = in_sizes[i_labels];
    int C = in_sizes[i_probs] / N;
    float* out = (float*)d_out;

    if (C == 100) {
        ece_main_c100<<<NBLK, 256>>>((const float4*)probs, labels, out, N);
    } else {
        ece_main_generic<<<NBLK, 256>>>(probs, labels, out, N, C);
    }
}